// round 8
// baseline (speedup 1.0000x reference)
#include <cuda_runtime.h>
#include <cuda_fp16.h>
#include <cstdint>

// Problem constants
#define NB      32
#define CDIM    256
#define HWN     4096
#define KCODES  1024
#define N_VEC   (NB * HWN)        // 131072
#define N_ZQ    (NB * CDIM * HWN) // 33554432

#define MARGIN  2.0e-3f           // ~7x worst-case |d_fast - d_ref| (f16 dot + fp32 bucket)

#define MT     128                // vectors per CTA
#define NSLICE 64                 // codes per slice
#define NSL    (KCODES / NSLICE)  // 16 slices

// ---------------- static device scratch (small!) ----------------
__device__ __half g_eh[KCODES * CDIM];   // f16 codebook [code][dim]  (512 KB)
__device__ float  g_se[KCODES];          // ||e||^2
__device__ int    g_idx[N_VEC];
__device__ double g_loss;

// ---------------- helpers ----------------
__device__ __forceinline__ uint32_t smem_u32(const void* p) {
    uint32_t a;
    asm("{ .reg .u64 t; cvta.to.shared.u64 t, %1; cvt.u32.u64 %0, t; }"
        : "=r"(a) : "l"(p));
    return a;
}
#define SW128(x) ((uint32_t)(x) ^ ((((uint32_t)(x)) >> 3) & 0x70u))

__device__ __forceinline__ void ldsm4(uint32_t* r, uint32_t addr) {
    asm volatile("ldmatrix.sync.aligned.m8n8.x4.shared.b16 {%0,%1,%2,%3}, [%4];"
                 : "=r"(r[0]), "=r"(r[1]), "=r"(r[2]), "=r"(r[3]) : "r"(addr));
}
__device__ __forceinline__ void mma16816(float* c, const uint32_t* a,
                                         uint32_t b0, uint32_t b1) {
    asm volatile("mma.sync.aligned.m16n8k16.row.col.f32.f16.f16.f32 "
                 "{%0,%1,%2,%3}, {%4,%5,%6,%7}, {%8,%9}, {%0,%1,%2,%3};"
                 : "+f"(c[0]), "+f"(c[1]), "+f"(c[2]), "+f"(c[3])
                 : "r"(a[0]), "r"(a[1]), "r"(a[2]), "r"(a[3]), "r"(b0), "r"(b1));
}
#define CP_ASYNC16(dst, src) \
    asm volatile("cp.async.cg.shared.global [%0], [%1], 16;" :: "r"(dst), "l"(src))
#define CP_COMMIT() asm volatile("cp.async.commit_group;" ::: "memory")
#define CP_WAIT0()  asm volatile("cp.async.wait_group 0;" ::: "memory")

// ---------------------------------------------------------------------------
// Codebook prep: f16 copy, ||e||^2, zero loss.
// ---------------------------------------------------------------------------
__global__ void cb_prep_kernel(const float* __restrict__ cb) {
    int n = blockIdx.x, t = threadIdx.x;
    float v = cb[n * CDIM + t];
    g_eh[n * CDIM + t] = __float2half(v);
    __shared__ float red[256];
    red[t] = __fmul_rn(v, v);
    __syncthreads();
    for (int s = 128; s > 0; s >>= 1) {
        if (t < s) red[t] = __fadd_rn(red[t], red[t + s]);
        __syncthreads();
    }
    if (t == 0) {
        g_se[n] = red[0];
        if (n == 0) g_loss = 0.0;
    }
}

// ---------------------------------------------------------------------------
// Main kernel: fully fused per-CTA VQ argmin for 128 vectors x 1024 codes.
// Phases: (1) load fp32 z chunks, in-CTA sz (ref order) + f16 convert;
//         (2) HMMA prefilter over 16 B slices (cp.async double-buffered);
//         (3) margin-candidate resolution + in-CTA exact rescore.
// ---------------------------------------------------------------------------
#define SM_Z   0         // 65536 : z f16, 4 chunks [128m][64k] SW128
#define SM_BB  65536     // 65536 : two 32KB B buffers; also fp32 staging in prep
#define SM_D   131072    // 34304 : dists 128 x 67 f32 (pitch 67: conflict-free)
#define SM_SE  165376    // 4096
#define SM_SZ  169472    // 512
#define SM_CD  169984    // 8192 (512 thr x 4 cand)
#define SM_CI  178176    // 8192
#define SM_TOT 186368
// overlays inside SM_D after the slice loop:
#define OV_MRG   (SM_D + 0)       // 512 x {runmin, cnt}
#define OV_PAIR  (SM_D + 4096)    // 2048 x u32
#define OV_OVF   (SM_D + 12288)   // 128 x u32
#define OV_KEY   (SM_D + 12800)   // 128 x u64
#define OV_SROW  (SM_D + 13824)   // 128 x int
#define OV_ACT   (SM_D + 14336)   // 128 x int
#define OV_CNT   (SM_D + 14848)   // 3 ints

__global__ void __launch_bounds__(512, 1)
vq_main_kernel(const float* __restrict__ z, const float* __restrict__ cb) {
    extern __shared__ __align__(1024) char sm[];
    const uint32_t sb = smem_u32(sm);
    const int tid = threadIdx.x;
    const int wid = tid >> 5, lane = tid & 31;
    const int wm = wid >> 2, wn = wid & 3;
    const int m0 = blockIdx.x * MT;
    const int b   = m0 >> 12;
    const int hw0 = m0 & (HWN - 1);

    float* seF = (float*)(sm + SM_SE);
    float* szF = (float*)(sm + SM_SZ);
    float* cdF = (float*)(sm + SM_CD);
    int*   ciI = (int*)(sm + SM_CI);
    float* z32 = (float*)(sm + SM_BB);   // staging [64c][132m] during prep

    for (int i = tid; i < KCODES; i += 512) seF[i] = g_se[i];

    // ---- Phase 1: z load + sz (ref order) + f16 convert ----
    float acc_sz = 0.0f;
    for (int cc = 0; cc < 4; cc++) {
        if (cc > 0) __syncthreads();   // staging consumers done
        // load [64 c][128 m] fp32, coalesced (m contiguous)
#pragma unroll
        for (int it = 0; it < 4; it++) {
            int idx = tid + it * 512;          // 2048 float4
            int c = idx >> 5, mq = idx & 31;
            float4 v = *(const float4*)(z +
                (((size_t)(b * CDIM + cc * 64 + c)) << 12) + hw0 + (mq << 2));
            *(float4*)(z32 + c * 132 + (mq << 2)) = v;
        }
        __syncthreads();
        // convert to f16 [m][k] chunk cc, SW128 (through-smem transpose)
#pragma unroll
        for (int t2 = 0; t2 < 2; t2++) {
            int task = tid + t2 * 512;         // 1024 tasks
            int m = task & 127, g = task >> 7; // g: 8-k group
            uint32_t u[4];
#pragma unroll
            for (int p = 0; p < 4; p++) {
                __half2 h2 = __floats2half2_rn(z32[(g * 8 + p * 2) * 132 + m],
                                               z32[(g * 8 + p * 2 + 1) * 132 + m]);
                u[p] = *(uint32_t*)&h2;
            }
            *(uint4*)(sm + SM_Z + cc * 16384 + SW128(m * 128 + g * 16)) =
                make_uint4(u[0], u[1], u[2], u[3]);
        }
        // sz partial: serial ascending c, unfused (reference order)
        if (tid < MT) {
            for (int c = 0; c < 64; c++) {
                float x = z32[c * 132 + tid];
                acc_sz = __fadd_rn(acc_sz, __fmul_rn(x, x));
            }
        }
    }
    __syncthreads();
    if (tid < MT) szF[tid] = acc_sz;

    // ---- load B slice 0 (staging region now free) ----
    {
        char* buf = sm + SM_BB;
#pragma unroll
        for (int it = 0; it < 4; it++) {
            int idx = tid + it * 512;          // 2048 uint4
            int kch = idx >> 9, w = idx & 511;
            int n = w >> 3, c8 = w & 7;
            uint4 v = *(const uint4*)(g_eh + (size_t)n * CDIM + kch * 64 + c8 * 8);
            *(uint4*)(buf + kch * 8192 + SW128(n * 128 + c8 * 16)) = v;
        }
    }
    __syncthreads();

    // per-thread persistent scan state: quarter sq of row srow
    const int srow = tid & 127, sq = tid >> 7;
    const float szr = szF[srow];
    float runmin = 3.4e38f;
    int cnt = 0;
    float* cd = cdF + tid * 4;
    int*   ci = ciI + tid * 4;

    const int q = lane >> 3, lr = lane & 7;
    const int arow = wm * 32 + ((q & 1) << 3) + lr;
    const int acol = (q >> 1) << 4;
    const int brow = wn * 16 + ((q >> 1) << 3) + lr;
    const int bcol = (q & 1) << 4;

    float* D = (float*)(sm + SM_D);

    // ---- Phase 2: 16 slices of 64 codes ----
    for (int ns = 0; ns < NSL; ns++) {
        // prefetch next slice into the other buffer
        if (ns + 1 < NSL) {
            uint32_t dstb = sb + SM_BB + ((ns + 1) & 1) * 32768;
#pragma unroll
            for (int it = 0; it < 4; it++) {
                int idx = tid + it * 512;
                int kch = idx >> 9, w = idx & 511;
                int n = w >> 3, c8 = w & 7;
                CP_ASYNC16(dstb + kch * 8192 + SW128(n * 128 + c8 * 16),
                           g_eh + (size_t)((ns + 1) * NSLICE + n) * CDIM + kch * 64 + c8 * 8);
            }
            CP_COMMIT();
        }

        float acc[2][2][4];
#pragma unroll
        for (int a = 0; a < 2; a++)
#pragma unroll
            for (int b2 = 0; b2 < 2; b2++)
#pragma unroll
                for (int c = 0; c < 4; c++) acc[a][b2][c] = 0.0f;

        const uint32_t bufb = sb + SM_BB + (ns & 1) * 32768;
#pragma unroll
        for (int k16 = 0; k16 < 16; k16++) {
            const uint32_t abase = sb + SM_Z + (k16 >> 2) * 16384;
            const uint32_t bbase = bufb + (k16 >> 2) * 8192;
            const int kb = (k16 & 3) * 32;
            uint32_t afr[2][4], bfr[4];
            ldsm4(afr[0], abase + SW128(arow * 128 + kb + acol));
            ldsm4(afr[1], abase + SW128((arow + 16) * 128 + kb + acol));
            ldsm4(bfr,    bbase + SW128(brow * 128 + kb + bcol));
#pragma unroll
            for (int mt = 0; mt < 2; mt++)
#pragma unroll
                for (int ni = 0; ni < 2; ni++)
                    mma16816(acc[mt][ni], afr[mt], bfr[ni * 2], bfr[ni * 2 + 1]);
        }
        __syncthreads();   // prev scan done -> D writable

        // dump dists (pitch 67)
        {
            const int g = lane >> 2, tg = lane & 3;
#pragma unroll
            for (int mt = 0; mt < 2; mt++) {
                int r0 = wm * 32 + mt * 16 + g;
#pragma unroll
                for (int ni = 0; ni < 2; ni++) {
                    int c = wn * 16 + ni * 8 + tg * 2;
                    D[r0 * 67 + c]           = acc[mt][ni][0];
                    D[r0 * 67 + c + 1]       = acc[mt][ni][1];
                    D[(r0 + 8) * 67 + c]     = acc[mt][ni][2];
                    D[(r0 + 8) * 67 + c + 1] = acc[mt][ni][3];
                }
            }
        }
        __syncthreads();   // D visible

        // scan: 4 threads/row, 16 codes each; state persists across slices
        {
            const int n0 = ns * NSLICE + sq * 16;
            const float* dr = D + srow * 67 + sq * 16;
            const float* ses = seF + n0;
#pragma unroll
            for (int j = 0; j < 16; j++) {
                float d = fmaf(-2.0f, dr[j], szr + ses[j]);
                if (d < runmin + MARGIN) {
                    runmin = fminf(runmin, d);
                    if (cnt < 4) { cd[cnt] = d; ci[cnt] = n0 + j; cnt++; }
                    else if (cnt == 4) {
                        int w = 0;
#pragma unroll
                        for (int t = 0; t < 4; t++)
                            if (cd[t] < runmin + MARGIN) { cd[w] = cd[t]; ci[w] = ci[t]; w++; }
                        cnt = w;
                        if (cnt < 4) { cd[cnt] = d; ci[cnt] = n0 + j; cnt++; }
                        else cnt = 5;  // overflow sentinel
                    }
                }
            }
        }
        if (ns + 1 < NSL) CP_WAIT0();
        __syncthreads();   // scan done, next B ready
    }

    // ---- Phase 3: in-CTA resolution (proven R7 logic) ----
    float* MRGf     = (float*)(sm + OV_MRG);
    uint32_t* pairs = (uint32_t*)(sm + OV_PAIR);
    uint32_t* ovfl  = (uint32_t*)(sm + OV_OVF);
    unsigned long long* keys = (unsigned long long*)(sm + OV_KEY);
    int* slotrow = (int*)(sm + OV_SROW);
    int* actA    = (int*)(sm + OV_ACT);
    int* cnt3    = (int*)(sm + OV_CNT);

    MRGf[tid * 2]     = runmin;
    MRGf[tid * 2 + 1] = __int_as_float(cnt);
    if (tid == 0) { cnt3[0] = 0; cnt3[1] = 0; cnt3[2] = 0; }
    __syncthreads();

    if (tid < MT) {
        const int r = tid;
        float gmin = 3.4e38f;
        bool ovf = false;
#pragma unroll
        for (int qq = 0; qq < 4; qq++) {
            int t2 = qq * 128 + r;
            gmin = fminf(gmin, MRGf[t2 * 2]);
            if (__float_as_int(MRGf[t2 * 2 + 1]) > 4) ovf = true;
        }
        if (ovf) {
            int slot = atomicAdd(&cnt3[0], 1);
            slotrow[slot] = r;
            int o = atomicAdd(&cnt3[2], 1);
            ovfl[o] = (uint32_t)((slot << 7) | r);
            actA[r] = 2;
        } else {
            int u = 0, uidx = 0;
#pragma unroll
            for (int qq = 0; qq < 4; qq++) {
                int t2 = qq * 128 + r;
                int c = __float_as_int(MRGf[t2 * 2 + 1]);
                for (int s = 0; s < c; s++)
                    if (cdF[t2 * 4 + s] < gmin + MARGIN) { u++; uidx = ciI[t2 * 4 + s]; }
            }
            if (u == 1) {
                g_idx[m0 + r] = uidx;
                actA[r] = 0;
            } else {
                actA[r] = 1;
                keys[r] = ~0ull;
                int slot = atomicAdd(&cnt3[0], 1);
                slotrow[slot] = r;
#pragma unroll
                for (int qq = 0; qq < 4; qq++) {
                    int t2 = qq * 128 + r;
                    int c = __float_as_int(MRGf[t2 * 2 + 1]);
                    for (int s = 0; s < c; s++)
                        if (cdF[t2 * 4 + s] < gmin + MARGIN) {
                            int p = atomicAdd(&cnt3[1], 1);
                            pairs[p] = (uint32_t)((slot << 17) | (r << 10) | ciI[t2 * 4 + s]);
                        }
                }
            }
        }
    }
    __syncthreads();

    const int nslots = cnt3[0], npairs = cnt3[1], novf = cnt3[2];
    float* stage = (float*)sm;   // overlays Z+B (128 KB): nslots x 256 f32

    // stage fp32 z rows for ambiguous rows (re-read from global, tiny volume)
    for (int i = tid; i < nslots * CDIM; i += 512) {
        int slot = i >> 8, c = i & 255;
        stage[slot * CDIM + c] =
            z[(((size_t)(b * CDIM + c)) << 12) + hw0 + slotrow[slot]];
    }
    __syncthreads();

    // exact pair rescore (bitwise reference recipe), thread per pair
    for (int p = tid; p < npairs; p += 512) {
        uint32_t e = pairs[p];
        int slot = (e >> 17) & 127, row = (e >> 10) & 127, code = e & 1023;
        const float* zs = stage + slot * CDIM;
        const float* er = cb + (size_t)code * CDIM;
        float acc2 = 0.0f;
#pragma unroll 16
        for (int k = 0; k < CDIM; k++) acc2 = __fmaf_rn(zs[k], __ldg(er + k), acc2);
        float d = __fsub_rn(__fadd_rn(szF[row], seF[code]), __fmul_rn(2.0f, acc2));
        unsigned long long kk =
            ((unsigned long long)__float_as_uint(d) << 32) | (unsigned)code;
        atomicMin(&keys[row], kk);
    }

    // exact full rescan for overflow rows, warp per row
    for (int o = wid; o < novf; o += 16) {
        uint32_t e = ovfl[o];
        int slot = e >> 7, row = e & 127;
        const float* zs = stage + slot * CDIM;
        float sz = szF[row];
        float bd = __int_as_float(0x7f800000);
        int bi = 0x7fffffff;
        for (int c = lane; c < KCODES; c += 32) {
            const float* er = cb + (size_t)c * CDIM;
            float acc2 = 0.0f;
#pragma unroll 16
            for (int k = 0; k < CDIM; k++) acc2 = __fmaf_rn(zs[k], __ldg(er + k), acc2);
            float d = __fsub_rn(__fadd_rn(sz, seF[c]), __fmul_rn(2.0f, acc2));
            if (d < bd) { bd = d; bi = c; }   // ascending c: strict < keeps lowest
        }
#pragma unroll
        for (int off = 16; off > 0; off >>= 1) {
            float od = __shfl_xor_sync(0xffffffffu, bd, off);
            int   oi = __shfl_xor_sync(0xffffffffu, bi, off);
            if (od < bd || (od == bd && oi < bi)) { bd = od; bi = oi; }
        }
        if (lane == 0) g_idx[m0 + row] = bi;
    }
    __syncthreads();

    if (tid < MT && actA[tid] == 1)
        g_idx[m0 + tid] = (int)(keys[tid] & 0xffffffffu);
}

// ---------------------------------------------------------------------------
// Gather + straight-through + loss (+ indices).  (proven exact)
// ---------------------------------------------------------------------------
__global__ void gather_kernel(const float* __restrict__ z,
                              const float* __restrict__ cb,
                              float* __restrict__ out, int mode) {
    int v  = blockIdx.x * blockDim.x + threadIdx.x;
    int b  = v >> 12, hw = v & (HWN - 1);
    int idx = g_idx[v];
    const float4* crow = (const float4*)(cb + idx * CDIM);
    float lsum = 0.0f;
    for (int cc = 0; cc < CDIM / 8; cc++) {
        float4 e0 = crow[cc * 2];
        float4 e1 = crow[cc * 2 + 1];
        float er[8] = {e0.x, e0.y, e0.z, e0.w, e1.x, e1.y, e1.z, e1.w};
#pragma unroll
        for (int j = 0; j < 8; j++) {
            int c = cc * 8 + j;
            size_t zi = (((size_t)b * CDIM + c) << 12) + hw;
            float zv = z[zi];
            float t  = __fsub_rn(er[j], zv);
            out[zi]  = __fadd_rn(zv, t);
            lsum = __fmaf_rn(t, t, lsum);
        }
    }
    for (int o = 16; o > 0; o >>= 1)
        lsum += __shfl_down_sync(0xffffffffu, lsum, o);
    if ((threadIdx.x & 31) == 0) atomicAdd(&g_loss, (double)lsum);
    if (mode >= 2) out[N_ZQ + 2 + v] = (float)idx;
}

__global__ void finalize_kernel(float* __restrict__ out, int mode) {
    if (mode >= 1) {
        float mean = (float)(g_loss / (double)N_ZQ);
        out[N_ZQ]     = mean;
        out[N_ZQ + 1] = 0.25f * mean;
    }
}

// ---------------------------------------------------------------------------
extern "C" void kernel_launch(void* const* d_in, const int* in_sizes, int n_in,
                              void* d_out, int out_size) {
    const float* z  = (const float*)d_in[0];
    const float* cb = (const float*)d_in[1];
    float* out = (float*)d_out;

    int mode = 0;
    if (out_size >= N_ZQ + 2) mode = 1;
    if (out_size >= N_ZQ + 2 + N_VEC) mode = 2;

    cudaFuncSetAttribute(vq_main_kernel,
                         cudaFuncAttributeMaxDynamicSharedMemorySize, SM_TOT);

    cb_prep_kernel<<<KCODES, 256>>>(cb);
    vq_main_kernel<<<N_VEC / MT, 512, SM_TOT>>>(z, cb);
    gather_kernel<<<N_VEC / 256, 256>>>(z, cb, out, mode);
    finalize_kernel<<<1, 1>>>(out, mode);
}

// round 9
// speedup vs baseline: 7.8732x; 7.8732x over previous
#include <cuda_runtime.h>
#include <cstdint>

// Problem constants
#define NB      32
#define CDIM    256
#define HWN     4096
#define KCODES  1024
#define N_VEC   (NB * HWN)        // 131072
#define N_ZQ    (NB * CDIM * HWN) // 33554432

#define NT_N    256               // codes per n-tile
#define NTILES  (KCODES / NT_N)   // 4
#define KC      16                // k per e-tile chunk
#define NKC     (CDIM / KC)       // 16 chunks per n-tile

// ---------------- static device scratch ----------------
// Duplicated codebook, lane-interleaved:
// f32 index = t*131072 + k*512 + w*64 + i*16 + s*4 + p*2 + {0,1}
//   (t = n>>8, n' = n&255, w = n'>>5, r = n'&31, i = r>>3, s = (r&7)>>1, p = r&1)
__device__ float  g_et2[KCODES * CDIM * 2];   // 2 MB
__device__ float  g_se[KCODES];               // ||e||^2
__device__ float  g_sz[N_VEC];                // ||z||^2 (ref order)
__device__ int    g_idx[N_VEC];
__device__ double g_loss;

#define FMA2(acc, a, b) \
    asm("fma.rn.f32x2 %0, %1, %2, %0;" : "+l"(acc) : "l"(a), "l"(b))

__device__ __forceinline__ uint32_t smem_u32(const void* p) {
    uint32_t a;
    asm("{ .reg .u64 t; cvta.to.shared.u64 t, %1; cvt.u32.u64 %0, t; }"
        : "=r"(a) : "l"(p));
    return a;
}
#define CP_ASYNC16(dst, src) \
    asm volatile("cp.async.cg.shared.global [%0], [%1], 16;" :: "r"(dst), "l"(src))
#define CP_COMMIT() asm volatile("cp.async.commit_group;" ::: "memory")
#define CP_WAIT(n)  asm volatile("cp.async.wait_group %0;" :: "n"(n) : "memory")

// ---------------------------------------------------------------------------
// Codebook prep: duplicated interleaved layout + ||e||^2 + zero loss.
// ---------------------------------------------------------------------------
__global__ void cb_prep_kernel(const float* __restrict__ cb) {
    int n = blockIdx.x, k = threadIdx.x;
    float v = cb[n * CDIM + k];
    int t = n >> 8, np = n & 255;
    int w = np >> 5, r = np & 31;
    int i = r >> 3, s = (r & 7) >> 1, p = r & 1;
    int off = t * 131072 + k * 512 + w * 64 + i * 16 + s * 4 + p * 2;
    g_et2[off]     = v;
    g_et2[off + 1] = v;
    __shared__ float red[256];
    red[k] = __fmul_rn(v, v);
    __syncthreads();
    for (int sft = 128; sft > 0; sft >>= 1) {
        if (k < sft) red[k] = __fadd_rn(red[k], red[k + sft]);
        __syncthreads();
    }
    if (k == 0) {
        g_se[n] = red[0];
        if (n == 0) g_loss = 0.0;
    }
}

// ---------------------------------------------------------------------------
// ||z||^2 in reference order (serial ascending, unfused).  (R3-proven)
// ---------------------------------------------------------------------------
__global__ void sz_kernel(const float* __restrict__ z) {
    int v  = blockIdx.x * blockDim.x + threadIdx.x;
    int b  = v >> 12, hw = v & (HWN - 1);
    const float* p = z + (size_t)b * CDIM * HWN + hw;
    float acc = 0.0f;
#pragma unroll 8
    for (int c = 0; c < CDIM; c++) {
        float x = __ldg(p + (size_t)c * HWN);
        acc = __fadd_rn(acc, __fmul_rn(x, x));
    }
    g_sz[v] = acc;
}

// ---------------------------------------------------------------------------
// Main fp32x2 GEMM + exact argmin. 256 threads, 128 vecs x 1024 codes / CTA.
// Per-thread 16m x 8n; A 4-way-broadcast LDS.128; B pre-duplicated LDS.128.
// Dot per element = single serial ascending-k fp32 FMA chain (bitwise ref).
// ---------------------------------------------------------------------------
#define SM_ZS  0                         // 131072 : z fp32 [256k][128m]
#define SM_ES  131072                    // 2 x 32768 : e-tiles (dup layout)
#define SM_SE  196608                    // 4096
#define SM_SZ  200704                    // 512
#define SM_TOT 201216
#define SM_RED SM_ES                     // overlay: 128 x 32 x 8B = 32768

__global__ void __launch_bounds__(256, 1)
vq_gemm_kernel(const float* __restrict__ z) {
    extern __shared__ __align__(1024) float smf[];
    char* sm = (char*)smf;
    const uint32_t sb = smem_u32(sm);
    const int tid  = threadIdx.x;
    const int w    = tid >> 5, lane = tid & 31;
    const int s    = lane >> 3;        // 0..3  (n sub-group)
    const int mc   = lane & 7;         // 0..7  (m chunk)
    const int m0 = blockIdx.x * 128;
    const int b   = m0 >> 12;
    const int hw0 = m0 & (HWN - 1);

    float* zS  = smf;                      // f32 units
    float* seS = (float*)(sm + SM_SE);
    float* szS = (float*)(sm + SM_SZ);

    for (int i = tid; i < KCODES; i += 256) seS[i] = g_se[i];
    if (tid < 128) szS[tid] = g_sz[m0 + tid];

    // z tile: [256 k][128 m] fp32, coalesced load, linear store
    for (int it = 0; it < 32; it++) {
        int idx = tid + it * 256;
        int c = idx >> 5, mq = idx & 31;
        float4 v = *(const float4*)(z + (((size_t)(b * CDIM + c)) << 12) + hw0 + (mq << 2));
        *(float4*)(zS + c * 128 + (mq << 2)) = v;
    }

    float bestd[16];
    int   besti[16];
#pragma unroll
    for (int i = 0; i < 16; i++) { bestd[i] = __int_as_float(0x7f800000); besti[i] = 0; }

    __syncthreads();

    for (int nt = 0; nt < NTILES; nt++) {
        // prefetch chunk 0 of this tile into buffer 0
        {
            const float* src = g_et2 + (size_t)nt * 131072;
#pragma unroll
            for (int it = 0; it < 8; it++) {
                int idx = tid + it * 256;
                CP_ASYNC16(sb + SM_ES + idx * 16, src + idx * 4);
            }
            CP_COMMIT();
        }

        unsigned long long acc[8][8];
#pragma unroll
        for (int a = 0; a < 8; a++)
#pragma unroll
            for (int c = 0; c < 8; c++) acc[a][c] = 0ull;

        for (int kc = 0; kc < NKC; kc++) {
            if (kc + 1 < NKC) {
                const float* src = g_et2 + (size_t)nt * 131072 + (size_t)(kc + 1) * KC * 512;
                uint32_t dst = sb + SM_ES + ((kc + 1) & 1) * 32768;
#pragma unroll
                for (int it = 0; it < 8; it++) {
                    int idx = tid + it * 256;
                    CP_ASYNC16(dst + idx * 16, src + idx * 4);
                }
                CP_COMMIT();
                CP_WAIT(1);   // chunk kc complete (kc+1 may be in flight)
            } else {
                CP_WAIT(0);
            }
            __syncthreads();  // e-tile kc visible to all

            const float* eT = (float*)(sm + SM_ES + (kc & 1) * 32768);
#pragma unroll 4
            for (int kk = 0; kk < KC; kk++) {
                const float* Ak = zS + (kc * KC + kk) * 128 + mc * 4;
                const float* Bk = eT + kk * 512 + w * 64 + s * 4;
                ulonglong2 A0 = *(const ulonglong2*)(Ak);        // chunk i=0
                ulonglong2 A1 = *(const ulonglong2*)(Ak + 32);   // i=1
                ulonglong2 A2 = *(const ulonglong2*)(Ak + 64);   // i=2
                ulonglong2 A3 = *(const ulonglong2*)(Ak + 96);   // i=3
                ulonglong2 B0 = *(const ulonglong2*)(Bk);        // n-pairs i=0
                ulonglong2 B1 = *(const ulonglong2*)(Bk + 16);
                ulonglong2 B2 = *(const ulonglong2*)(Bk + 32);
                ulonglong2 B3 = *(const ulonglong2*)(Bk + 48);
                unsigned long long av[8] = {A0.x, A0.y, A1.x, A1.y, A2.x, A2.y, A3.x, A3.y};
                unsigned long long bv[8] = {B0.x, B0.y, B1.x, B1.y, B2.x, B2.y, B3.x, B3.y};
#pragma unroll
                for (int a = 0; a < 8; a++)
#pragma unroll
                    for (int c = 0; c < 8; c++)
                        FMA2(acc[a][c], av[a], bv[c]);
            }
            __syncthreads();  // compute done before buffer reuse (kc+2 overwrite)
        }

        // epilogue: d = fl(fl(sz+se) - 2*dot), running argmin, ascending n
#pragma unroll
        for (int ib = 0; ib < 4; ib++)
#pragma unroll
            for (int p = 0; p < 2; p++) {
                const int n = nt * NT_N + w * 32 + ib * 8 + s * 2 + p;
                const float se = seS[n];
#pragma unroll
                for (int ia = 0; ia < 4; ia++)
#pragma unroll
                    for (int h = 0; h < 2; h++) {
                        unsigned long long pk = acc[ia * 2 + h][ib * 2 + p];
                        float dlo = __uint_as_float((unsigned)(pk & 0xffffffffu));
                        float dhi = __uint_as_float((unsigned)(pk >> 32));
                        int mb = (ia * 8 + mc) * 4 + h * 2;     // global m (lo)
                        int li = ia * 4 + h * 2;                // local best slot
                        float d0 = __fsub_rn(__fadd_rn(szS[mb],     se), __fmul_rn(2.0f, dlo));
                        float d1 = __fsub_rn(__fadd_rn(szS[mb + 1], se), __fmul_rn(2.0f, dhi));
                        if (d0 < bestd[li])     { bestd[li]     = d0; besti[li]     = n; }
                        if (d1 < bestd[li + 1]) { bestd[li + 1] = d1; besti[li + 1] = n; }
                    }
            }
    }

    // cross-thread reduction: 32 participants (w,s) per m row
    __syncthreads();
    float* redD = (float*)(sm + SM_RED);            // [128][32] d
    int*   redI = (int*)(sm + SM_RED + 16384);      // [128][32] idx
    const int pid = w * 4 + s;
#pragma unroll
    for (int ia = 0; ia < 4; ia++)
#pragma unroll
        for (int h = 0; h < 2; h++)
#pragma unroll
            for (int e = 0; e < 2; e++) {
                int m  = (ia * 8 + mc) * 4 + h * 2 + e;
                int li = ia * 4 + h * 2 + e;
                redD[m * 32 + pid] = bestd[li];
                redI[m * 32 + pid] = besti[li];
            }
    __syncthreads();
    if (tid < 128) {
        float bv = redD[tid * 32];
        int   bi = redI[tid * 32];
#pragma unroll
        for (int t = 1; t < 32; t++) {
            float v  = redD[tid * 32 + t];
            int   ix = redI[tid * 32 + t];
            if (v < bv || (v == bv && ix < bi)) { bv = v; bi = ix; }
        }
        g_idx[m0 + tid] = bi;
    }
}

// ---------------------------------------------------------------------------
// Gather + straight-through + loss (+ indices).  (R3-proven)
// ---------------------------------------------------------------------------
__global__ void gather_kernel(const float* __restrict__ z,
                              const float* __restrict__ cb,
                              float* __restrict__ out, int mode) {
    int v  = blockIdx.x * blockDim.x + threadIdx.x;
    int b  = v >> 12, hw = v & (HWN - 1);
    int idx = g_idx[v];
    const float4* crow = (const float4*)(cb + idx * CDIM);
    float lsum = 0.0f;
    for (int cc = 0; cc < CDIM / 8; cc++) {
        float4 e0 = crow[cc * 2];
        float4 e1 = crow[cc * 2 + 1];
        float er[8] = {e0.x, e0.y, e0.z, e0.w, e1.x, e1.y, e1.z, e1.w};
#pragma unroll
        for (int j = 0; j < 8; j++) {
            int c = cc * 8 + j;
            size_t zi = (((size_t)b * CDIM + c) << 12) + hw;
            float zv = z[zi];
            float t  = __fsub_rn(er[j], zv);
            out[zi]  = __fadd_rn(zv, t);
            lsum = __fmaf_rn(t, t, lsum);
        }
    }
    for (int o = 16; o > 0; o >>= 1)
        lsum += __shfl_down_sync(0xffffffffu, lsum, o);
    if ((threadIdx.x & 31) == 0) atomicAdd(&g_loss, (double)lsum);
    if (mode >= 2) out[N_ZQ + 2 + v] = (float)idx;
}

__global__ void finalize_kernel(float* __restrict__ out, int mode) {
    if (mode >= 1) {
        float mean = (float)(g_loss / (double)N_ZQ);
        out[N_ZQ]     = mean;
        out[N_ZQ + 1] = 0.25f * mean;
    }
}

// ---------------------------------------------------------------------------
extern "C" void kernel_launch(void* const* d_in, const int* in_sizes, int n_in,
                              void* d_out, int out_size) {
    const float* z  = (const float*)d_in[0];
    const float* cb = (const float*)d_in[1];
    float* out = (float*)d_out;

    int mode = 0;
    if (out_size >= N_ZQ + 2) mode = 1;
    if (out_size >= N_ZQ + 2 + N_VEC) mode = 2;

    cudaFuncSetAttribute(vq_gemm_kernel,
                         cudaFuncAttributeMaxDynamicSharedMemorySize, SM_TOT);

    cb_prep_kernel<<<KCODES, 256>>>(cb);
    sz_kernel<<<N_VEC / 256, 256>>>(z);
    vq_gemm_kernel<<<N_VEC / 128, 256, SM_TOT>>>(z);
    gather_kernel<<<N_VEC / 256, 256>>>(z, cb, out, mode);
    finalize_kernel<<<1, 1>>>(out, mode);
}

// round 10
// speedup vs baseline: 8.0364x; 1.0207x over previous
#include <cuda_runtime.h>
#include <cstdint>

// Problem constants
#define NB      32
#define CDIM    256
#define HWN     4096
#define KCODES  1024
#define N_VEC   (NB * HWN)        // 131072
#define N_ZQ    (NB * CDIM * HWN) // 33554432

#define NT_N    256               // codes per n-tile
#define NTILES  (KCODES / NT_N)   // 4
#define KC      16                // k per e-tile chunk
#define NKC     (CDIM / KC)       // 16 chunks per n-tile

// ---------------- static device scratch ----------------
// Duplicated codebook, lane-interleaved:
// f32 index = t*131072 + k*512 + w*64 + i*16 + s*4 + p*2 + {0,1}
__device__ float  g_et2[KCODES * CDIM * 2];   // 2 MB
__device__ float  g_se[KCODES];               // ||e||^2
__device__ double g_loss;

#define FMA2(acc, a, b) \
    asm("fma.rn.f32x2 %0, %1, %2, %0;" : "+l"(acc) : "l"(a), "l"(b))

__device__ __forceinline__ uint32_t smem_u32(const void* p) {
    uint32_t a;
    asm("{ .reg .u64 t; cvta.to.shared.u64 t, %1; cvt.u32.u64 %0, t; }"
        : "=r"(a) : "l"(p));
    return a;
}
#define CP_ASYNC16(dst, src) \
    asm volatile("cp.async.cg.shared.global [%0], [%1], 16;" :: "r"(dst), "l"(src))
#define CP_COMMIT() asm volatile("cp.async.commit_group;" ::: "memory")
#define CP_WAIT(n)  asm volatile("cp.async.wait_group %0;" :: "n"(n) : "memory")

// ---------------------------------------------------------------------------
// Codebook prep: duplicated interleaved layout + ||e||^2 + zero loss.
// ---------------------------------------------------------------------------
__global__ void cb_prep_kernel(const float* __restrict__ cb) {
    int n = blockIdx.x, k = threadIdx.x;
    float v = cb[n * CDIM + k];
    int t = n >> 8, np = n & 255;
    int w = np >> 5, r = np & 31;
    int i = r >> 3, s = (r & 7) >> 1, p = r & 1;
    int off = t * 131072 + k * 512 + w * 64 + i * 16 + s * 4 + p * 2;
    g_et2[off]     = v;
    g_et2[off + 1] = v;
    __shared__ float red[256];
    red[k] = __fmul_rn(v, v);
    __syncthreads();
    for (int sft = 128; sft > 0; sft >>= 1) {
        if (k < sft) red[k] = __fadd_rn(red[k], red[k + sft]);
        __syncthreads();
    }
    if (k == 0) {
        g_se[n] = red[0];
        if (n == 0) g_loss = 0.0;
    }
}

// ---------------------------------------------------------------------------
// Fused kernel: fp32x2 GEMM + exact argmin + sz + gather/loss/indices.
// 256 threads, 128 vecs x 1024 codes per CTA. GEMM core identical to R9.
// ---------------------------------------------------------------------------
#define SM_ZS  0                         // 131072 : z fp32 [256k][128m]
#define SM_ES  131072                    // 2 x 32768 : e-tiles (dup layout)
#define SM_SE  196608                    // 4096
#define SM_SZ  200704                    // 512
#define SM_IDX 201216                    // 512
#define SM_TOT 201728
#define SM_RED SM_ES                     // overlay: 128 x 32 x 8B = 32768

__global__ void __launch_bounds__(256, 1)
vq_gemm_kernel(const float* __restrict__ z, const float* __restrict__ cb,
               float* __restrict__ out, int mode) {
    extern __shared__ __align__(1024) float smf[];
    char* sm = (char*)smf;
    const uint32_t sb = smem_u32(sm);
    const int tid  = threadIdx.x;
    const int w    = tid >> 5, lane = tid & 31;
    const int s    = lane >> 3;        // 0..3  (n sub-group)
    const int mc   = lane & 7;         // 0..7  (m chunk)
    const int m0 = blockIdx.x * 128;
    const int b   = m0 >> 12;
    const int hw0 = m0 & (HWN - 1);

    float* zS  = smf;
    float* seS = (float*)(sm + SM_SE);
    float* szS = (float*)(sm + SM_SZ);
    int*   idxS = (int*)(sm + SM_IDX);

    for (int i = tid; i < KCODES; i += 256) seS[i] = g_se[i];

    // z tile: [256 k][128 m] fp32, coalesced load, linear store
    for (int it = 0; it < 32; it++) {
        int idx = tid + it * 256;
        int c = idx >> 5, mq = idx & 31;
        float4 v = *(const float4*)(z + (((size_t)(b * CDIM + c)) << 12) + hw0 + (mq << 2));
        *(float4*)(zS + c * 128 + (mq << 2)) = v;
    }
    __syncthreads();

    // ||z||^2 in reference order: serial ascending c, unfused mul+add
    if (tid < 128) {
        float a = 0.0f;
        for (int c = 0; c < CDIM; c++) {
            float x = zS[c * 128 + tid];
            a = __fadd_rn(a, __fmul_rn(x, x));
        }
        szS[tid] = a;
    }

    float bestd[16];
    int   besti[16];
#pragma unroll
    for (int i = 0; i < 16; i++) { bestd[i] = __int_as_float(0x7f800000); besti[i] = 0; }

    __syncthreads();

    for (int nt = 0; nt < NTILES; nt++) {
        // prefetch chunk 0 of this tile into buffer 0
        {
            const float* src = g_et2 + (size_t)nt * 131072;
#pragma unroll
            for (int it = 0; it < 8; it++) {
                int idx = tid + it * 256;
                CP_ASYNC16(sb + SM_ES + idx * 16, src + idx * 4);
            }
            CP_COMMIT();
        }

        unsigned long long acc[8][8];
#pragma unroll
        for (int a = 0; a < 8; a++)
#pragma unroll
            for (int c = 0; c < 8; c++) acc[a][c] = 0ull;

        for (int kc = 0; kc < NKC; kc++) {
            if (kc + 1 < NKC) {
                const float* src = g_et2 + (size_t)nt * 131072 + (size_t)(kc + 1) * KC * 512;
                uint32_t dst = sb + SM_ES + ((kc + 1) & 1) * 32768;
#pragma unroll
                for (int it = 0; it < 8; it++) {
                    int idx = tid + it * 256;
                    CP_ASYNC16(dst + idx * 16, src + idx * 4);
                }
                CP_COMMIT();
                CP_WAIT(1);   // chunk kc complete (kc+1 may be in flight)
            } else {
                CP_WAIT(0);
            }
            __syncthreads();  // e-tile kc visible to all

            const float* eT = (float*)(sm + SM_ES + (kc & 1) * 32768);
#pragma unroll 4
            for (int kk = 0; kk < KC; kk++) {
                const float* Ak = zS + (kc * KC + kk) * 128 + mc * 4;
                const float* Bk = eT + kk * 512 + w * 64 + s * 4;
                ulonglong2 A0 = *(const ulonglong2*)(Ak);
                ulonglong2 A1 = *(const ulonglong2*)(Ak + 32);
                ulonglong2 A2 = *(const ulonglong2*)(Ak + 64);
                ulonglong2 A3 = *(const ulonglong2*)(Ak + 96);
                ulonglong2 B0 = *(const ulonglong2*)(Bk);
                ulonglong2 B1 = *(const ulonglong2*)(Bk + 16);
                ulonglong2 B2 = *(const ulonglong2*)(Bk + 32);
                ulonglong2 B3 = *(const ulonglong2*)(Bk + 48);
                unsigned long long av[8] = {A0.x, A0.y, A1.x, A1.y, A2.x, A2.y, A3.x, A3.y};
                unsigned long long bv[8] = {B0.x, B0.y, B1.x, B1.y, B2.x, B2.y, B3.x, B3.y};
#pragma unroll
                for (int a = 0; a < 8; a++)
#pragma unroll
                    for (int c = 0; c < 8; c++)
                        FMA2(acc[a][c], av[a], bv[c]);
            }
            __syncthreads();  // compute done before buffer reuse
        }

        // epilogue: d = fl(fl(sz+se) - 2*dot), running argmin, ascending n
#pragma unroll
        for (int ib = 0; ib < 4; ib++)
#pragma unroll
            for (int p = 0; p < 2; p++) {
                const int n = nt * NT_N + w * 32 + ib * 8 + s * 2 + p;
                const float se = seS[n];
#pragma unroll
                for (int ia = 0; ia < 4; ia++)
#pragma unroll
                    for (int h = 0; h < 2; h++) {
                        unsigned long long pk = acc[ia * 2 + h][ib * 2 + p];
                        float dlo = __uint_as_float((unsigned)(pk & 0xffffffffu));
                        float dhi = __uint_as_float((unsigned)(pk >> 32));
                        int mb = (ia * 8 + mc) * 4 + h * 2;
                        int li = ia * 4 + h * 2;
                        float d0 = __fsub_rn(__fadd_rn(szS[mb],     se), __fmul_rn(2.0f, dlo));
                        float d1 = __fsub_rn(__fadd_rn(szS[mb + 1], se), __fmul_rn(2.0f, dhi));
                        if (d0 < bestd[li])     { bestd[li]     = d0; besti[li]     = n; }
                        if (d1 < bestd[li + 1]) { bestd[li + 1] = d1; besti[li + 1] = n; }
                    }
            }
    }

    // cross-thread reduction: 32 participants (w,s) per m row
    __syncthreads();
    float* redD = (float*)(sm + SM_RED);            // [128][32] d
    int*   redI = (int*)(sm + SM_RED + 16384);      // [128][32] idx
    const int pid = w * 4 + s;
#pragma unroll
    for (int ia = 0; ia < 4; ia++)
#pragma unroll
        for (int h = 0; h < 2; h++)
#pragma unroll
            for (int e = 0; e < 2; e++) {
                int m  = (ia * 8 + mc) * 4 + h * 2 + e;
                int li = ia * 4 + h * 2 + e;
                redD[m * 32 + pid] = bestd[li];
                redI[m * 32 + pid] = besti[li];
            }
    __syncthreads();
    if (tid < 128) {
        float bv = redD[tid * 32];
        int   bi = redI[tid * 32];
#pragma unroll
        for (int t = 1; t < 32; t++) {
            float v  = redD[tid * 32 + t];
            int   ix = redI[tid * 32 + t];
            if (v < bv || (v == bv && ix < bi)) { bv = v; bi = ix; }
        }
        idxS[tid] = bi;
        if (mode >= 2) out[N_ZQ + 2 + m0 + tid] = (float)bi;
    }
    __syncthreads();

    // ---- fused gather: z from smem, e from L2, coalesced 128B stores ----
    {
        const int gm = tid & 127, gh = tid >> 7;   // row, column-half
        const int idx = idxS[gm];
        const float4* er4 = (const float4*)(cb + (size_t)idx * CDIM) + gh * 32;
        float lsum = 0.0f;
#pragma unroll 4
        for (int cq = 0; cq < 32; cq++) {
            float4 e4 = er4[cq];
            int c0 = gh * 128 + cq * 4;
            float ev[4] = {e4.x, e4.y, e4.z, e4.w};
#pragma unroll
            for (int j = 0; j < 4; j++) {
                int c = c0 + j;
                float zv = zS[c * 128 + gm];
                float t  = __fsub_rn(ev[j], zv);           // e - z
                out[(((size_t)(b * CDIM + c)) << 12) + hw0 + gm] = __fadd_rn(zv, t);
                lsum = __fmaf_rn(t, t, lsum);
            }
        }
        for (int o = 16; o > 0; o >>= 1)
            lsum += __shfl_down_sync(0xffffffffu, lsum, o);
        if (lane == 0) atomicAdd(&g_loss, (double)lsum);
    }
}

__global__ void finalize_kernel(float* __restrict__ out, int mode) {
    if (mode >= 1) {
        float mean = (float)(g_loss / (double)N_ZQ);
        out[N_ZQ]     = mean;          // codebook_loss
        out[N_ZQ + 1] = 0.25f * mean;  // commitment_loss = exactly 0.25 * mean
    }
}

// ---------------------------------------------------------------------------
extern "C" void kernel_launch(void* const* d_in, const int* in_sizes, int n_in,
                              void* d_out, int out_size) {
    const float* z  = (const float*)d_in[0];
    const float* cb = (const float*)d_in[1];
    float* out = (float*)d_out;

    int mode = 0;
    if (out_size >= N_ZQ + 2) mode = 1;
    if (out_size >= N_ZQ + 2 + N_VEC) mode = 2;

    cudaFuncSetAttribute(vq_gemm_kernel,
                         cudaFuncAttributeMaxDynamicSharedMemorySize, SM_TOT);

    cb_prep_kernel<<<KCODES, 256>>>(cb);
    vq_gemm_kernel<<<N_VEC / 128, 256, SM_TOT>>>(z, cb, out, mode);
    finalize_kernel<<<1, 1>>>(out, mode);
}